// round 1
// baseline (speedup 1.0000x reference)
#include <cuda_runtime.h>
#include <cuda_bf16.h>

// VariableSelectionNetwork: B=32, S=512, F=32, H=64
//   transformed = features[...,None]*W_feat + b_feat        [B,S,F,H]
//   gates = softmax(flat @ W_gate + b_gate)                 [B,S,F]
//   out   = einsum('bsfh,bsf->bsh', transformed, gates)     [B,S,H]
//
// Restructured:
//   A[f][g] = sum_h W_feat[f,h] * W_gate[f*H+h, g]          (32x32)
//   c[g]    = b_gate[g] + sum_i b_feat[i] * W_gate[i, g]    (32)
//   logits  = x @ A + c ; g = softmax(logits)
//   out     = (g*x) @ W_feat + g @ b_feat

#define F_DIM 32
#define H_DIM 64
#define ROWS  16384   // B*S

// Scratch (no allocations allowed in kernel_launch)
__device__ float g_A[F_DIM * F_DIM];      // A[f][g]
__device__ float g_Cpart[F_DIM * F_DIM];  // per-f partial of c: Cpart[f][g]

// ---------------------------------------------------------------------------
// Prep: 32 blocks (one per f), 256 threads (8 h-segments x 32 g).
// Each block reads its 64-row slice of W_gate once and produces both
// A[f][:] and Cpart[f][:].
// ---------------------------------------------------------------------------
__global__ void __launch_bounds__(256) vsn_prep_kernel(
    const float* __restrict__ W_feat,   // [32,64]
    const float* __restrict__ b_feat,   // [32,64]
    const float* __restrict__ W_gate)   // [2048,32]
{
    const int f  = blockIdx.x;
    const int g  = threadIdx.x & 31;
    const int hs = threadIdx.x >> 5;    // 0..7

    float a = 0.f, c = 0.f;
#pragma unroll
    for (int k = 0; k < 8; k++) {
        const int h = hs * 8 + k;
        const float wg = W_gate[(f * H_DIM + h) * F_DIM + g];
        a = fmaf(W_feat[f * H_DIM + h], wg, a);
        c = fmaf(b_feat[f * H_DIM + h], wg, c);
    }

    __shared__ float sA[8][32];
    __shared__ float sC[8][32];
    sA[hs][g] = a;
    sC[hs][g] = c;
    __syncthreads();

    if (threadIdx.x < 32) {
        float as = 0.f, cs = 0.f;
#pragma unroll
        for (int r = 0; r < 8; r++) { as += sA[r][threadIdx.x]; cs += sC[r][threadIdx.x]; }
        g_A[f * F_DIM + threadIdx.x]     = as;
        g_Cpart[f * F_DIM + threadIdx.x] = cs;
    }
}

// ---------------------------------------------------------------------------
// Main: 256 blocks x 256 threads. 4 threads (one quad) per row -> 64 rows/block.
// Thread role q = tid&3: owns logits [q*8, q*8+8) and output cols [q*16, q*16+16).
// ---------------------------------------------------------------------------
__global__ void __launch_bounds__(256) vsn_main_kernel(
    const float* __restrict__ features,  // [16384, 32]
    const float* __restrict__ W_feat,    // [32, 64]
    const float* __restrict__ b_feat,    // [32, 64]
    const float* __restrict__ b_gate,    // [32]
    float* __restrict__ out)             // [16384, 64]
{
    __shared__ float sW[F_DIM * H_DIM];  // 8 KB
    __shared__ float sB[F_DIM * H_DIM];  // 8 KB
    __shared__ float sA[F_DIM * F_DIM];  // 4 KB
    __shared__ float sc[F_DIM];          // 128 B

    const int tid = threadIdx.x;

    // Stage params into smem
    {
        const float4* wf4 = (const float4*)W_feat;
        const float4* bf4 = (const float4*)b_feat;
        float4* sw4 = (float4*)sW;
        float4* sb4 = (float4*)sB;
#pragma unroll
        for (int i = tid; i < (F_DIM * H_DIM) / 4; i += 256) {
            sw4[i] = wf4[i];
            sb4[i] = bf4[i];
        }
        if (tid < (F_DIM * F_DIM) / 4) {
            ((float4*)sA)[tid] = ((const float4*)g_A)[tid];
        }
        if (tid < 32) {
            float cv = b_gate[tid];
#pragma unroll
            for (int f = 0; f < F_DIM; f++) cv += g_Cpart[f * F_DIM + tid];
            sc[tid] = cv;
        }
    }
    __syncthreads();

    const int quad = tid >> 2;            // 0..63: row within block
    const int q    = tid & 3;             // role within quad
    const int lane = tid & 31;
    const int row  = blockIdx.x * 64 + quad;   // 256*64 = 16384 exactly

    // Load this row's features (all 32) into registers
    float x[F_DIM];
    {
        const float4* xr = (const float4*)(features + row * F_DIM);
#pragma unroll
        for (int i = 0; i < F_DIM / 4; i++) {
            float4 v = xr[i];
            x[4 * i + 0] = v.x; x[4 * i + 1] = v.y;
            x[4 * i + 2] = v.z; x[4 * i + 3] = v.w;
        }
    }

    // ---- Phase 1: logits l[8] = x @ A[:, q*8 : q*8+8] + c ----
    float l[8];
#pragma unroll
    for (int j = 0; j < 8; j++) l[j] = sc[q * 8 + j];
#pragma unroll
    for (int f = 0; f < F_DIM; f++) {
        const float xf = x[f];
        const float* arow = sA + f * F_DIM + q * 8;
#pragma unroll
        for (int j = 0; j < 8; j++) l[j] = fmaf(xf, arow[j], l[j]);
    }

    // ---- Softmax over the 32 logits held by the quad ----
    float m = l[0];
#pragma unroll
    for (int j = 1; j < 8; j++) m = fmaxf(m, l[j]);
    m = fmaxf(m, __shfl_xor_sync(0xffffffffu, m, 1));
    m = fmaxf(m, __shfl_xor_sync(0xffffffffu, m, 2));

    float s = 0.f;
#pragma unroll
    for (int j = 0; j < 8; j++) { l[j] = __expf(l[j] - m); s += l[j]; }
    s += __shfl_xor_sync(0xffffffffu, s, 1);
    s += __shfl_xor_sync(0xffffffffu, s, 2);

    const float inv = 1.f / s;
#pragma unroll
    for (int j = 0; j < 8; j++) l[j] *= inv;   // l[] now holds gates g[q*8+j]

    // ---- Phase 2: out[hbase..hbase+16) = sum_f (g[f]*x[f])*W[f,h] + g[f]*b[f,h]
    const int hbase = q * 16;
    float o[16];
#pragma unroll
    for (int j = 0; j < 16; j++) o[j] = 0.f;

#pragma unroll
    for (int f = 0; f < F_DIM; f++) {
        const int src = f >> 3;                          // compile-time under unroll
        const float gf = __shfl_sync(0xffffffffu, l[f & 7], (lane & ~3) | src);
        const float gx = gf * x[f];
        const float* wrow = sW + f * H_DIM + hbase;
        const float* brow = sB + f * H_DIM + hbase;
#pragma unroll
        for (int j = 0; j < 16; j++) {
            o[j] = fmaf(gx, wrow[j], fmaf(gf, brow[j], o[j]));
        }
    }

    // Store 16 contiguous floats (64B aligned)
    float4* op = (float4*)(out + row * H_DIM + hbase);
#pragma unroll
    for (int j = 0; j < 4; j++) {
        op[j] = make_float4(o[4 * j + 0], o[4 * j + 1], o[4 * j + 2], o[4 * j + 3]);
    }
}

extern "C" void kernel_launch(void* const* d_in, const int* in_sizes, int n_in,
                              void* d_out, int out_size)
{
    const float* features = (const float*)d_in[0];   // [32,512,32]
    const float* W_feat   = (const float*)d_in[1];   // [32,64]
    const float* b_feat   = (const float*)d_in[2];   // [32,64]
    const float* W_gate   = (const float*)d_in[3];   // [2048,32]
    const float* b_gate   = (const float*)d_in[4];   // [32]
    float* out = (float*)d_out;                      // [32,512,64]

    vsn_prep_kernel<<<32, 256>>>(W_feat, b_feat, W_gate);
    vsn_main_kernel<<<256, 256>>>(features, W_feat, b_feat, b_gate, out);
}